// round 10
// baseline (speedup 1.0000x reference)
#include <cuda_runtime.h>
#include <cuda_fp16.h>

#define BB 4
#define NN 10000
#define CC 128
#define KK 16
#define OC 128
#define C2 256        // 2*C
#define TILE 64       // nodes per CTA
#define NPW 8         // nodes per warp (phase 1)
#define NTHREADS 256  // 8 warps
#define PITCH 264     // fp16 elems per feat row (256 + 8 pad -> conflict-free LDSM)

// fp16 copy of x: [B][N][C]
__device__ __half g_xh[BB * NN * CC];

// Arranged fp16 weight fragments for mma.m16n8k16 (B col-major fragment):
// g_Wb2[ktile*16+ntile][lane] = uint2{ b0, b1 }
//   b0 = half2( Wd[k0+(lane%4)*2][n], Wd[k0+(lane%4)*2+1][n] )
//   b1 = same with k0+8,  n = ntile*8 + lane/4
// Wd[c2][o]: c2<128 -> W[o][2*c2] (self), c2>=128 -> W[o][2*(c2-128)+1] (rel)
__device__ uint2 g_Wb2[16 * 16 * 32];

__global__ void convert_x_kernel(const float* __restrict__ x) {
    int idx = blockIdx.x * blockDim.x + threadIdx.x;  // one float4 per thread
    const int total4 = BB * NN * CC / 4;
    if (idx < total4) {
        float4 v = __ldg((const float4*)x + idx);
        __half2 h0 = __floats2half2_rn(v.x, v.y);
        __half2 h1 = __floats2half2_rn(v.z, v.w);
        uint2 r;
        r.x = *reinterpret_cast<unsigned*>(&h0);
        r.y = *reinterpret_cast<unsigned*>(&h1);
        ((uint2*)g_xh)[idx] = r;
    }
}

__global__ void arrange_W_kernel(const float* __restrict__ W) {
    int tid = blockIdx.x * blockDim.x + threadIdx.x;   // 8192 threads
    if (tid >= 16 * 16 * 32) return;
    int lane  = tid & 31;
    int ntile = (tid >> 5) & 15;
    int ktile = tid >> 9;

    int n  = ntile * 8 + (lane >> 2);
    int k0 = ktile * 16 + (lane & 3) * 2;

    float wv[4];
    int kk[4] = {k0, k0 + 1, k0 + 8, k0 + 9};
    #pragma unroll
    for (int i = 0; i < 4; ++i) {
        int c2 = kk[i];
        int src_c = (c2 < CC) ? (2 * c2) : (2 * (c2 - CC) + 1);
        wv[i] = W[n * C2 + src_c];
    }
    __half2 b0 = __floats2half2_rn(wv[0], wv[1]);
    __half2 b1 = __floats2half2_rn(wv[2], wv[3]);
    uint2 r;
    r.x = *reinterpret_cast<unsigned*>(&b0);
    r.y = *reinterpret_cast<unsigned*>(&b1);
    g_Wb2[tid] = r;
}

__device__ __forceinline__ void mma_f16(float* d, unsigned a0, unsigned a1,
                                        unsigned a2, unsigned a3,
                                        unsigned b0, unsigned b1) {
    asm volatile(
        "mma.sync.aligned.m16n8k16.row.col.f32.f16.f16.f32 "
        "{%0,%1,%2,%3}, {%4,%5,%6,%7}, {%8,%9}, {%0,%1,%2,%3};"
        : "+f"(d[0]), "+f"(d[1]), "+f"(d[2]), "+f"(d[3])
        : "r"(a0), "r"(a1), "r"(a2), "r"(a3), "r"(b0), "r"(b1));
}

__device__ __forceinline__ void ldsm_x4(unsigned& r0, unsigned& r1,
                                        unsigned& r2, unsigned& r3, unsigned addr) {
    asm volatile("ldmatrix.sync.aligned.m8n8.x4.shared.b16 {%0,%1,%2,%3}, [%4];"
                 : "=r"(r0), "=r"(r1), "=r"(r2), "=r"(r3) : "r"(addr));
}

__global__ void __launch_bounds__(NTHREADS, 4)
mrconv_kernel(const int*   __restrict__ edge,
              const float* __restrict__ bias,
              float*       __restrict__ out) {
    __shared__ __half feat_s[TILE][PITCH];  // [0,128)=self, [128,256)=rel

    const int b     = blockIdx.y;
    const int tile0 = blockIdx.x * TILE;
    const int warp  = threadIdx.x >> 5;
    const int lane  = threadIdx.x & 31;

    const __half* __restrict__ xb = g_xh + (size_t)b * NN * CC;

    // ---------------- Phase 1: gather + max-relative, 8 nodes per warp ----
    for (int i = 0; i < NPW; ++i) {
        const int nl = warp * NPW + i;
        const int n  = tile0 + nl;
        uint2* hs = (uint2*)&feat_s[nl][4 * lane];        // self channels
        uint2* hr = (uint2*)&feat_s[nl][CC + 4 * lane];   // rel channels
        if (n >= NN) {
            uint2 z = make_uint2(0u, 0u);
            *hs = z; *hr = z;
            continue;
        }
        // lanes 0..15 hold edge[0][...k] (j), lanes 16..31 hold edge[1][...k] (i)
        const int s = lane >> 4;
        const int k = lane & 15;
        const int idx = __ldg(&edge[(((size_t)s * BB + b) * NN + n) * KK + k]);

        const uint2 xs = __ldg((const uint2*)(xb + (size_t)n * CC) + lane);

        __half2 rel0 = *reinterpret_cast<const __half2*>(&(unsigned){0xFC00FC00u});
        __half2 rel1 = rel0;
        #pragma unroll 8
        for (int kk = 0; kk < KK; ++kk) {
            const int jn = __shfl_sync(0xffffffffu, idx, kk);        // edge[0]
            const int im = __shfl_sync(0xffffffffu, idx, kk + 16);   // edge[1]
            const uint2 vj = __ldg((const uint2*)(xb + (size_t)jn * CC) + lane);
            const uint2 vi = __ldg((const uint2*)(xb + (size_t)im * CC) + lane);
            __half2 d0 = __hsub2(*(const __half2*)&vj.x, *(const __half2*)&vi.x);
            __half2 d1 = __hsub2(*(const __half2*)&vj.y, *(const __half2*)&vi.y);
            rel0 = __hmax2(rel0, d0);
            rel1 = __hmax2(rel1, d1);
        }
        *hs = xs;
        uint2 rr;
        rr.x = *reinterpret_cast<unsigned*>(&rel0);
        rr.y = *reinterpret_cast<unsigned*>(&rel1);
        *hr = rr;
    }
    __syncthreads();

    // ---------------- Phase 2: tensor-core GEMM ---------------------------
    // warp -> M-tile (16 nodes) x 64 output cols (8 n-tiles of 8)
    const int mtile = warp & 3;           // 0..3 -> nodes mtile*16..+15
    const int nhalf = warp >> 2;          // 0..1 -> out cols nhalf*64..+63

    float acc[8][4];
    #pragma unroll
    for (int t = 0; t < 8; ++t)
        #pragma unroll
        for (int j = 0; j < 4; ++j) acc[t][j] = 0.f;

    const int rowA = mtile * 16 + ((lane >> 3) & 1) * 8 + (lane & 7);
    const int kofs = (lane >= 16) ? 8 : 0;
    unsigned aAddr = (unsigned)__cvta_generic_to_shared(&feat_s[rowA][kofs]);

    const uint2* __restrict__ Wb = g_Wb2;

    #pragma unroll 4
    for (int kt = 0; kt < 16; ++kt) {
        unsigned h0, h1, h2, h3;
        ldsm_x4(h0, h1, h2, h3, aAddr + kt * 32);   // 16 fp16 * 2B per kt
        #pragma unroll
        for (int nt = 0; nt < 8; ++nt) {
            const uint2 wb = __ldg(&Wb[((kt * 16) + (nhalf * 8 + nt)) * 32 + lane]);
            mma_f16(acc[nt], h0, h1, h2, h3, wb.x, wb.y);
        }
    }

    // ---------------- Epilogue: bias + relu + store -----------------------
    const int grp = lane >> 2;            // row within 8
    const int cid = (lane & 3) * 2;       // col pair base
    #pragma unroll
    for (int nt = 0; nt < 8; ++nt) {
        const int ncol = nhalf * 64 + nt * 8 + cid;
        const float2 bv = __ldg((const float2*)(bias + ncol));
        #pragma unroll
        for (int half = 0; half < 2; ++half) {
            const int n = tile0 + mtile * 16 + grp + half * 8;
            if (n < NN) {
                float2 o2;
                o2.x = fmaxf(acc[nt][2 * half + 0] + bv.x, 0.f);
                o2.y = fmaxf(acc[nt][2 * half + 1] + bv.y, 0.f);
                *(float2*)(out + ((size_t)b * NN + n) * OC + ncol) = o2;
            }
        }
    }
}

extern "C" void kernel_launch(void* const* d_in, const int* in_sizes, int n_in,
                              void* d_out, int out_size) {
    const float* x    = (const float*)d_in[0];  // [4,10000,128] f32
    const int*   edge = (const int*)  d_in[1];  // [2,4,10000,16] i32
    const float* W    = (const float*)d_in[2];  // [128,256] f32
    const float* bias = (const float*)d_in[3];  // [128] f32
    float* out = (float*)d_out;                 // [4,10000,128] f32

    const int total4 = BB * NN * CC / 4;
    convert_x_kernel<<<(total4 + 255) / 256, 256>>>(x);
    arrange_W_kernel<<<32, 256>>>(W);

    dim3 grid((NN + TILE - 1) / TILE, BB);
    mrconv_kernel<<<grid, NTHREADS>>>(edge, bias, out);
}

// round 11
// speedup vs baseline: 1.3935x; 1.3935x over previous
#include <cuda_runtime.h>
#include <cuda_fp16.h>

#define BB 4
#define NN 10000
#define CC 128
#define KK 16
#define OC 128
#define C2 256        // 2*C
#define TILE 64       // nodes per CTA
#define NPW 8         // nodes per warp (phase 1)
#define NTHREADS 256  // 8 warps
#define PITCH 264     // fp16 elems per feat row (256 + 8 pad -> conflict-free LDSM)

// fp16 copy of x: [B][N][C]
__device__ __half g_xh[BB * NN * CC];

// Arranged fp16 weight fragments for mma.m16n8k16 (B col-major fragment):
// g_Wb2[ktile*16+ntile][lane] = uint2{ b0, b1 }
//   b0 = half2( Wd[k0+(lane%4)*2][n], Wd[k0+(lane%4)*2+1][n] )
//   b1 = same with k0+8,  n = ntile*8 + lane/4
// Wd[c2][o]: c2<128 -> W[o][2*c2] (self), c2>=128 -> W[o][2*(c2-128)+1] (rel)
__device__ uint2 g_Wb2[16 * 16 * 32];

__global__ void convert_x_kernel(const float* __restrict__ x) {
    int idx = blockIdx.x * blockDim.x + threadIdx.x;  // one float4 per thread
    const int total4 = BB * NN * CC / 4;
    if (idx < total4) {
        float4 v = __ldg((const float4*)x + idx);
        __half2 h0 = __floats2half2_rn(v.x, v.y);
        __half2 h1 = __floats2half2_rn(v.z, v.w);
        uint2 r;
        r.x = *reinterpret_cast<unsigned*>(&h0);
        r.y = *reinterpret_cast<unsigned*>(&h1);
        ((uint2*)g_xh)[idx] = r;
    }
}

__global__ void arrange_W_kernel(const float* __restrict__ W) {
    int tid = blockIdx.x * blockDim.x + threadIdx.x;   // 8192 threads
    if (tid >= 16 * 16 * 32) return;
    int lane  = tid & 31;
    int ntile = (tid >> 5) & 15;
    int ktile = tid >> 9;

    int n  = ntile * 8 + (lane >> 2);
    int k0 = ktile * 16 + (lane & 3) * 2;

    float wv[4];
    int kk[4] = {k0, k0 + 1, k0 + 8, k0 + 9};
    #pragma unroll
    for (int i = 0; i < 4; ++i) {
        int c2 = kk[i];
        int src_c = (c2 < CC) ? (2 * c2) : (2 * (c2 - CC) + 1);
        wv[i] = W[n * C2 + src_c];
    }
    __half2 b0 = __floats2half2_rn(wv[0], wv[1]);
    __half2 b1 = __floats2half2_rn(wv[2], wv[3]);
    uint2 r;
    r.x = *reinterpret_cast<unsigned*>(&b0);
    r.y = *reinterpret_cast<unsigned*>(&b1);
    g_Wb2[tid] = r;
}

__device__ __forceinline__ void mma_f16(float* d, unsigned a0, unsigned a1,
                                        unsigned a2, unsigned a3,
                                        unsigned b0, unsigned b1) {
    asm volatile(
        "mma.sync.aligned.m16n8k16.row.col.f32.f16.f16.f32 "
        "{%0,%1,%2,%3}, {%4,%5,%6,%7}, {%8,%9}, {%0,%1,%2,%3};"
        : "+f"(d[0]), "+f"(d[1]), "+f"(d[2]), "+f"(d[3])
        : "r"(a0), "r"(a1), "r"(a2), "r"(a3), "r"(b0), "r"(b1));
}

__device__ __forceinline__ void ldsm_x4(unsigned& r0, unsigned& r1,
                                        unsigned& r2, unsigned& r3, unsigned addr) {
    asm volatile("ldmatrix.sync.aligned.m8n8.x4.shared.b16 {%0,%1,%2,%3}, [%4];"
                 : "=r"(r0), "=r"(r1), "=r"(r2), "=r"(r3) : "r"(addr));
}

__global__ void __launch_bounds__(NTHREADS, 4)
mrconv_kernel(const int*   __restrict__ edge,
              const float* __restrict__ bias,
              float*       __restrict__ out) {
    __shared__ __half feat_s[TILE][PITCH];  // [0,128)=self, [128,256)=rel

    const int b     = blockIdx.y;
    const int tile0 = blockIdx.x * TILE;
    const int warp  = threadIdx.x >> 5;
    const int lane  = threadIdx.x & 31;

    const __half* __restrict__ xb = g_xh + (size_t)b * NN * CC;

    // ---------------- Phase 1: gather + max-relative, 8 nodes per warp ----
    for (int i = 0; i < NPW; ++i) {
        const int nl = warp * NPW + i;
        const int n  = tile0 + nl;
        uint2* hs = (uint2*)&feat_s[nl][4 * lane];        // self channels
        uint2* hr = (uint2*)&feat_s[nl][CC + 4 * lane];   // rel channels
        if (n >= NN) {
            uint2 z = make_uint2(0u, 0u);
            *hs = z; *hr = z;
            continue;
        }
        // lanes 0..15 hold edge[0][...k] (j), lanes 16..31 hold edge[1][...k] (i)
        const int s = lane >> 4;
        const int k = lane & 15;
        const int idx = __ldg(&edge[(((size_t)s * BB + b) * NN + n) * KK + k]);

        const uint2 xs = __ldg((const uint2*)(xb + (size_t)n * CC) + lane);

        __half2 rel0 = *reinterpret_cast<const __half2*>(&(unsigned){0xFC00FC00u});
        __half2 rel1 = rel0;
        #pragma unroll 8
        for (int kk = 0; kk < KK; ++kk) {
            const int jn = __shfl_sync(0xffffffffu, idx, kk);        // edge[0]
            const int im = __shfl_sync(0xffffffffu, idx, kk + 16);   // edge[1]
            const uint2 vj = __ldg((const uint2*)(xb + (size_t)jn * CC) + lane);
            const uint2 vi = __ldg((const uint2*)(xb + (size_t)im * CC) + lane);
            __half2 d0 = __hsub2(*(const __half2*)&vj.x, *(const __half2*)&vi.x);
            __half2 d1 = __hsub2(*(const __half2*)&vj.y, *(const __half2*)&vi.y);
            rel0 = __hmax2(rel0, d0);
            rel1 = __hmax2(rel1, d1);
        }
        *hs = xs;
        uint2 rr;
        rr.x = *reinterpret_cast<unsigned*>(&rel0);
        rr.y = *reinterpret_cast<unsigned*>(&rel1);
        *hr = rr;
    }
    __syncthreads();

    // ---------------- Phase 2: tensor-core GEMM ---------------------------
    // warp -> M-tile (16 nodes) x 64 output cols (8 n-tiles of 8)
    const int mtile = warp & 3;           // 0..3 -> nodes mtile*16..+15
    const int nhalf = warp >> 2;          // 0..1 -> out cols nhalf*64..+63

    float acc[8][4];
    #pragma unroll
    for (int t = 0; t < 8; ++t)
        #pragma unroll
        for (int j = 0; j < 4; ++j) acc[t][j] = 0.f;

    const int rowA = mtile * 16 + ((lane >> 3) & 1) * 8 + (lane & 7);
    const int kofs = (lane >= 16) ? 8 : 0;
    unsigned aAddr = (unsigned)__cvta_generic_to_shared(&feat_s[rowA][kofs]);

    const uint2* __restrict__ Wb = g_Wb2;

    #pragma unroll 4
    for (int kt = 0; kt < 16; ++kt) {
        unsigned h0, h1, h2, h3;
        ldsm_x4(h0, h1, h2, h3, aAddr + kt * 32);   // 16 fp16 * 2B per kt
        #pragma unroll
        for (int nt = 0; nt < 8; ++nt) {
            const uint2 wb = __ldg(&Wb[((kt * 16) + (nhalf * 8 + nt)) * 32 + lane]);
            mma_f16(acc[nt], h0, h1, h2, h3, wb.x, wb.y);
        }
    }

    // ---------------- Epilogue: bias + relu + store -----------------------
    const int grp = lane >> 2;            // row within 8
    const int cid = (lane & 3) * 2;       // col pair base
    #pragma unroll
    for (int nt = 0; nt < 8; ++nt) {
        const int ncol = nhalf * 64 + nt * 8 + cid;
        const float2 bv = __ldg((const float2*)(bias + ncol));
        #pragma unroll
        for (int half = 0; half < 2; ++half) {
            const int n = tile0 + mtile * 16 + grp + half * 8;
            if (n < NN) {
                float2 o2;
                o2.x = fmaxf(acc[nt][2 * half + 0] + bv.x, 0.f);
                o2.y = fmaxf(acc[nt][2 * half + 1] + bv.y, 0.f);
                *(float2*)(out + ((size_t)b * NN + n) * OC + ncol) = o2;
            }
        }
    }
}

extern "C" void kernel_launch(void* const* d_in, const int* in_sizes, int n_in,
                              void* d_out, int out_size) {
    const float* x    = (const float*)d_in[0];  // [4,10000,128] f32
    const int*   edge = (const int*)  d_in[1];  // [2,4,10000,16] i32
    const float* W    = (const float*)d_in[2];  // [128,256] f32
    const float* bias = (const float*)d_in[3];  // [128] f32
    float* out = (float*)d_out;                 // [4,10000,128] f32

    const int total4 = BB * NN * CC / 4;
    convert_x_kernel<<<(total4 + 255) / 256, 256>>>(x);
    arrange_W_kernel<<<32, 256>>>(W);

    dim3 grid((NN + TILE - 1) / TILE, BB);
    mrconv_kernel<<<grid, NTHREADS>>>(edge, bias, out);
}

// round 12
// speedup vs baseline: 1.3969x; 1.0025x over previous
#include <cuda_runtime.h>
#include <cuda_fp16.h>

#define BB 4
#define NN 10000
#define CC 128
#define KK 16
#define OC 128
#define C2 256        // 2*C
#define TILE 64       // nodes per CTA
#define NPW 8         // nodes per warp (phase 1)
#define NTHREADS 256  // 8 warps
#define PITCH 264     // fp16 elems per feat row (256 + 8 pad -> conflict-free LDSM)

// fp16 copy of x: [B][N][C]
__device__ __half g_xh[BB * NN * CC];

// Arranged fp16 weight fragments for mma.m16n8k16 (B col-major fragment):
// g_Wb2[ktile*16+ntile][lane] = uint2{ b0, b1 }
//   b0 = half2( Wd[k0+(lane%4)*2][n], Wd[k0+(lane%4)*2+1][n] )
//   b1 = same with k0+8,  n = ntile*8 + lane/4
// Wd[c2][o]: c2<128 -> W[o][2*c2] (self), c2>=128 -> W[o][2*(c2-128)+1] (rel)
__device__ uint2 g_Wb2[16 * 16 * 32];

__global__ void convert_x_kernel(const float* __restrict__ x) {
    int idx = blockIdx.x * blockDim.x + threadIdx.x;  // one float4 per thread
    const int total4 = BB * NN * CC / 4;
    if (idx < total4) {
        float4 v = __ldg((const float4*)x + idx);
        __half2 h0 = __floats2half2_rn(v.x, v.y);
        __half2 h1 = __floats2half2_rn(v.z, v.w);
        uint2 r;
        r.x = *reinterpret_cast<unsigned*>(&h0);
        r.y = *reinterpret_cast<unsigned*>(&h1);
        ((uint2*)g_xh)[idx] = r;
    }
}

__global__ void arrange_W_kernel(const float* __restrict__ W) {
    int tid = blockIdx.x * blockDim.x + threadIdx.x;   // 8192 threads
    if (tid >= 16 * 16 * 32) return;
    int lane  = tid & 31;
    int ntile = (tid >> 5) & 15;
    int ktile = tid >> 9;

    int n  = ntile * 8 + (lane >> 2);
    int k0 = ktile * 16 + (lane & 3) * 2;

    float wv[4];
    int kk[4] = {k0, k0 + 1, k0 + 8, k0 + 9};
    #pragma unroll
    for (int i = 0; i < 4; ++i) {
        int c2 = kk[i];
        int src_c = (c2 < CC) ? (2 * c2) : (2 * (c2 - CC) + 1);
        wv[i] = W[n * C2 + src_c];
    }
    __half2 b0 = __floats2half2_rn(wv[0], wv[1]);
    __half2 b1 = __floats2half2_rn(wv[2], wv[3]);
    uint2 r;
    r.x = *reinterpret_cast<unsigned*>(&b0);
    r.y = *reinterpret_cast<unsigned*>(&b1);
    g_Wb2[tid] = r;
}

__device__ __forceinline__ void mma_f16(float* d, unsigned a0, unsigned a1,
                                        unsigned a2, unsigned a3,
                                        unsigned b0, unsigned b1) {
    asm volatile(
        "mma.sync.aligned.m16n8k16.row.col.f32.f16.f16.f32 "
        "{%0,%1,%2,%3}, {%4,%5,%6,%7}, {%8,%9}, {%0,%1,%2,%3};"
        : "+f"(d[0]), "+f"(d[1]), "+f"(d[2]), "+f"(d[3])
        : "r"(a0), "r"(a1), "r"(a2), "r"(a3), "r"(b0), "r"(b1));
}

__device__ __forceinline__ void ldsm_x4(unsigned& r0, unsigned& r1,
                                        unsigned& r2, unsigned& r3, unsigned addr) {
    asm volatile("ldmatrix.sync.aligned.m8n8.x4.shared.b16 {%0,%1,%2,%3}, [%4];"
                 : "=r"(r0), "=r"(r1), "=r"(r2), "=r"(r3) : "r"(addr));
}

__global__ void __launch_bounds__(NTHREADS, 4)
mrconv_kernel(const int*   __restrict__ edge,
              const float* __restrict__ bias,
              float*       __restrict__ out) {
    __shared__ __half feat_s[TILE][PITCH];  // [0,128)=self, [128,256)=rel

    const int b     = blockIdx.y;
    const int tile0 = blockIdx.x * TILE;
    const int warp  = threadIdx.x >> 5;
    const int lane  = threadIdx.x & 31;

    const __half* __restrict__ xb = g_xh + (size_t)b * NN * CC;

    // ---------------- Phase 1: gather + max-relative, 8 nodes per warp ----
    for (int i = 0; i < NPW; ++i) {
        const int nl = warp * NPW + i;
        const int n  = tile0 + nl;
        uint2* hs = (uint2*)&feat_s[nl][4 * lane];        // self channels
        uint2* hr = (uint2*)&feat_s[nl][CC + 4 * lane];   // rel channels
        if (n >= NN) {
            uint2 z = make_uint2(0u, 0u);
            *hs = z; *hr = z;
            continue;
        }
        // lanes 0..15 hold edge[0][...k] (j), lanes 16..31 hold edge[1][...k] (i)
        const int s = lane >> 4;
        const int k = lane & 15;
        const int idx = __ldg(&edge[(((size_t)s * BB + b) * NN + n) * KK + k]);

        const uint2 xs = __ldg((const uint2*)(xb + (size_t)n * CC) + lane);

        __half2 rel0 = *reinterpret_cast<const __half2*>(&(unsigned){0xFC00FC00u});
        __half2 rel1 = rel0;
        #pragma unroll 8
        for (int kk = 0; kk < KK; ++kk) {
            const int jn = __shfl_sync(0xffffffffu, idx, kk);        // edge[0]
            const int im = __shfl_sync(0xffffffffu, idx, kk + 16);   // edge[1]
            const uint2 vj = __ldg((const uint2*)(xb + (size_t)jn * CC) + lane);
            const uint2 vi = __ldg((const uint2*)(xb + (size_t)im * CC) + lane);
            __half2 d0 = __hsub2(*(const __half2*)&vj.x, *(const __half2*)&vi.x);
            __half2 d1 = __hsub2(*(const __half2*)&vj.y, *(const __half2*)&vi.y);
            rel0 = __hmax2(rel0, d0);
            rel1 = __hmax2(rel1, d1);
        }
        *hs = xs;
        uint2 rr;
        rr.x = *reinterpret_cast<unsigned*>(&rel0);
        rr.y = *reinterpret_cast<unsigned*>(&rel1);
        *hr = rr;
    }
    __syncthreads();

    // ---------------- Phase 2: tensor-core GEMM ---------------------------
    // warp -> M-tile (16 nodes) x 64 output cols (8 n-tiles of 8)
    const int mtile = warp & 3;           // 0..3 -> nodes mtile*16..+15
    const int nhalf = warp >> 2;          // 0..1 -> out cols nhalf*64..+63

    float acc[8][4];
    #pragma unroll
    for (int t = 0; t < 8; ++t)
        #pragma unroll
        for (int j = 0; j < 4; ++j) acc[t][j] = 0.f;

    const int rowA = mtile * 16 + ((lane >> 3) & 1) * 8 + (lane & 7);
    const int kofs = (lane >= 16) ? 8 : 0;
    unsigned aAddr = (unsigned)__cvta_generic_to_shared(&feat_s[rowA][kofs]);

    const uint2* __restrict__ Wb = g_Wb2;

    #pragma unroll 4
    for (int kt = 0; kt < 16; ++kt) {
        unsigned h0, h1, h2, h3;
        ldsm_x4(h0, h1, h2, h3, aAddr + kt * 32);   // 16 fp16 * 2B per kt
        #pragma unroll
        for (int nt = 0; nt < 8; ++nt) {
            const uint2 wb = __ldg(&Wb[((kt * 16) + (nhalf * 8 + nt)) * 32 + lane]);
            mma_f16(acc[nt], h0, h1, h2, h3, wb.x, wb.y);
        }
    }

    // ---------------- Epilogue: bias + relu + store -----------------------
    const int grp = lane >> 2;            // row within 8
    const int cid = (lane & 3) * 2;       // col pair base
    #pragma unroll
    for (int nt = 0; nt < 8; ++nt) {
        const int ncol = nhalf * 64 + nt * 8 + cid;
        const float2 bv = __ldg((const float2*)(bias + ncol));
        #pragma unroll
        for (int half = 0; half < 2; ++half) {
            const int n = tile0 + mtile * 16 + grp + half * 8;
            if (n < NN) {
                float2 o2;
                o2.x = fmaxf(acc[nt][2 * half + 0] + bv.x, 0.f);
                o2.y = fmaxf(acc[nt][2 * half + 1] + bv.y, 0.f);
                *(float2*)(out + ((size_t)b * NN + n) * OC + ncol) = o2;
            }
        }
    }
}

extern "C" void kernel_launch(void* const* d_in, const int* in_sizes, int n_in,
                              void* d_out, int out_size) {
    const float* x    = (const float*)d_in[0];  // [4,10000,128] f32
    const int*   edge = (const int*)  d_in[1];  // [2,4,10000,16] i32
    const float* W    = (const float*)d_in[2];  // [128,256] f32
    const float* bias = (const float*)d_in[3];  // [128] f32
    float* out = (float*)d_out;                 // [4,10000,128] f32

    const int total4 = BB * NN * CC / 4;
    convert_x_kernel<<<(total4 + 255) / 256, 256>>>(x);
    arrange_W_kernel<<<32, 256>>>(W);

    dim3 grid((NN + TILE - 1) / TILE, BB);
    mrconv_kernel<<<grid, NTHREADS>>>(edge, bias, out);
}

// round 13
// speedup vs baseline: 1.3986x; 1.0012x over previous
#include <cuda_runtime.h>
#include <cuda_fp16.h>

#define BB 4
#define NN 10000
#define CC 128
#define KK 16
#define OC 128
#define C2 256        // 2*C
#define TILE 64       // nodes per CTA
#define NPW 8         // nodes per warp (phase 1)
#define NTHREADS 256  // 8 warps
#define PITCH 264     // fp16 elems per feat row (256 + 8 pad -> conflict-free LDSM)

// fp16 copy of x: [B][N][C]
__device__ __half g_xh[BB * NN * CC];

// Arranged fp16 weight fragments for mma.m16n8k16 (B col-major fragment):
// g_Wb2[ktile*16+ntile][lane] = uint2{ b0, b1 }
//   b0 = half2( Wd[k0+(lane%4)*2][n], Wd[k0+(lane%4)*2+1][n] )
//   b1 = same with k0+8,  n = ntile*8 + lane/4
// Wd[c2][o]: c2<128 -> W[o][2*c2] (self), c2>=128 -> W[o][2*(c2-128)+1] (rel)
__device__ uint2 g_Wb2[16 * 16 * 32];

__global__ void convert_x_kernel(const float* __restrict__ x) {
    int idx = blockIdx.x * blockDim.x + threadIdx.x;  // one float4 per thread
    const int total4 = BB * NN * CC / 4;
    if (idx < total4) {
        float4 v = __ldg((const float4*)x + idx);
        __half2 h0 = __floats2half2_rn(v.x, v.y);
        __half2 h1 = __floats2half2_rn(v.z, v.w);
        uint2 r;
        r.x = *reinterpret_cast<unsigned*>(&h0);
        r.y = *reinterpret_cast<unsigned*>(&h1);
        ((uint2*)g_xh)[idx] = r;
    }
}

__global__ void arrange_W_kernel(const float* __restrict__ W) {
    int tid = blockIdx.x * blockDim.x + threadIdx.x;   // 8192 threads
    if (tid >= 16 * 16 * 32) return;
    int lane  = tid & 31;
    int ntile = (tid >> 5) & 15;
    int ktile = tid >> 9;

    int n  = ntile * 8 + (lane >> 2);
    int k0 = ktile * 16 + (lane & 3) * 2;

    float wv[4];
    int kk[4] = {k0, k0 + 1, k0 + 8, k0 + 9};
    #pragma unroll
    for (int i = 0; i < 4; ++i) {
        int c2 = kk[i];
        int src_c = (c2 < CC) ? (2 * c2) : (2 * (c2 - CC) + 1);
        wv[i] = W[n * C2 + src_c];
    }
    __half2 b0 = __floats2half2_rn(wv[0], wv[1]);
    __half2 b1 = __floats2half2_rn(wv[2], wv[3]);
    uint2 r;
    r.x = *reinterpret_cast<unsigned*>(&b0);
    r.y = *reinterpret_cast<unsigned*>(&b1);
    g_Wb2[tid] = r;
}

__device__ __forceinline__ void mma_f16(float* d, unsigned a0, unsigned a1,
                                        unsigned a2, unsigned a3,
                                        unsigned b0, unsigned b1) {
    asm volatile(
        "mma.sync.aligned.m16n8k16.row.col.f32.f16.f16.f32 "
        "{%0,%1,%2,%3}, {%4,%5,%6,%7}, {%8,%9}, {%0,%1,%2,%3};"
        : "+f"(d[0]), "+f"(d[1]), "+f"(d[2]), "+f"(d[3])
        : "r"(a0), "r"(a1), "r"(a2), "r"(a3), "r"(b0), "r"(b1));
}

__device__ __forceinline__ void ldsm_x4(unsigned& r0, unsigned& r1,
                                        unsigned& r2, unsigned& r3, unsigned addr) {
    asm volatile("ldmatrix.sync.aligned.m8n8.x4.shared.b16 {%0,%1,%2,%3}, [%4];"
                 : "=r"(r0), "=r"(r1), "=r"(r2), "=r"(r3) : "r"(addr));
}

__global__ void __launch_bounds__(NTHREADS, 4)
mrconv_kernel(const int*   __restrict__ edge,
              const float* __restrict__ bias,
              float*       __restrict__ out) {
    __shared__ __half feat_s[TILE][PITCH];  // [0,128)=self, [128,256)=rel

    const int b     = blockIdx.y;
    const int tile0 = blockIdx.x * TILE;
    const int warp  = threadIdx.x >> 5;
    const int lane  = threadIdx.x & 31;

    const __half* __restrict__ xb = g_xh + (size_t)b * NN * CC;

    // ---------------- Phase 1: gather + max-relative, 8 nodes per warp ----
    for (int i = 0; i < NPW; ++i) {
        const int nl = warp * NPW + i;
        const int n  = tile0 + nl;
        uint2* hs = (uint2*)&feat_s[nl][4 * lane];        // self channels
        uint2* hr = (uint2*)&feat_s[nl][CC + 4 * lane];   // rel channels
        if (n >= NN) {
            uint2 z = make_uint2(0u, 0u);
            *hs = z; *hr = z;
            continue;
        }
        // lanes 0..15 hold edge[0][...k] (j), lanes 16..31 hold edge[1][...k] (i)
        const int s = lane >> 4;
        const int k = lane & 15;
        const int idx = __ldg(&edge[(((size_t)s * BB + b) * NN + n) * KK + k]);

        const uint2 xs = __ldg((const uint2*)(xb + (size_t)n * CC) + lane);

        __half2 rel0 = *reinterpret_cast<const __half2*>(&(unsigned){0xFC00FC00u});
        __half2 rel1 = rel0;
        #pragma unroll 8
        for (int kk = 0; kk < KK; ++kk) {
            const int jn = __shfl_sync(0xffffffffu, idx, kk);        // edge[0]
            const int im = __shfl_sync(0xffffffffu, idx, kk + 16);   // edge[1]
            const uint2 vj = __ldg((const uint2*)(xb + (size_t)jn * CC) + lane);
            const uint2 vi = __ldg((const uint2*)(xb + (size_t)im * CC) + lane);
            __half2 d0 = __hsub2(*(const __half2*)&vj.x, *(const __half2*)&vi.x);
            __half2 d1 = __hsub2(*(const __half2*)&vj.y, *(const __half2*)&vi.y);
            rel0 = __hmax2(rel0, d0);
            rel1 = __hmax2(rel1, d1);
        }
        *hs = xs;
        uint2 rr;
        rr.x = *reinterpret_cast<unsigned*>(&rel0);
        rr.y = *reinterpret_cast<unsigned*>(&rel1);
        *hr = rr;
    }
    __syncthreads();

    // ---------------- Phase 2: tensor-core GEMM ---------------------------
    // warp -> M-tile (16 nodes) x 64 output cols (8 n-tiles of 8)
    const int mtile = warp & 3;           // 0..3 -> nodes mtile*16..+15
    const int nhalf = warp >> 2;          // 0..1 -> out cols nhalf*64..+63

    float acc[8][4];
    #pragma unroll
    for (int t = 0; t < 8; ++t)
        #pragma unroll
        for (int j = 0; j < 4; ++j) acc[t][j] = 0.f;

    const int rowA = mtile * 16 + ((lane >> 3) & 1) * 8 + (lane & 7);
    const int kofs = (lane >= 16) ? 8 : 0;
    unsigned aAddr = (unsigned)__cvta_generic_to_shared(&feat_s[rowA][kofs]);

    const uint2* __restrict__ Wb = g_Wb2;

    #pragma unroll 4
    for (int kt = 0; kt < 16; ++kt) {
        unsigned h0, h1, h2, h3;
        ldsm_x4(h0, h1, h2, h3, aAddr + kt * 32);   // 16 fp16 * 2B per kt
        #pragma unroll
        for (int nt = 0; nt < 8; ++nt) {
            const uint2 wb = __ldg(&Wb[((kt * 16) + (nhalf * 8 + nt)) * 32 + lane]);
            mma_f16(acc[nt], h0, h1, h2, h3, wb.x, wb.y);
        }
    }

    // ---------------- Epilogue: bias + relu + store -----------------------
    const int grp = lane >> 2;            // row within 8
    const int cid = (lane & 3) * 2;       // col pair base
    #pragma unroll
    for (int nt = 0; nt < 8; ++nt) {
        const int ncol = nhalf * 64 + nt * 8 + cid;
        const float2 bv = __ldg((const float2*)(bias + ncol));
        #pragma unroll
        for (int half = 0; half < 2; ++half) {
            const int n = tile0 + mtile * 16 + grp + half * 8;
            if (n < NN) {
                float2 o2;
                o2.x = fmaxf(acc[nt][2 * half + 0] + bv.x, 0.f);
                o2.y = fmaxf(acc[nt][2 * half + 1] + bv.y, 0.f);
                *(float2*)(out + ((size_t)b * NN + n) * OC + ncol) = o2;
            }
        }
    }
}

extern "C" void kernel_launch(void* const* d_in, const int* in_sizes, int n_in,
                              void* d_out, int out_size) {
    const float* x    = (const float*)d_in[0];  // [4,10000,128] f32
    const int*   edge = (const int*)  d_in[1];  // [2,4,10000,16] i32
    const float* W    = (const float*)d_in[2];  // [128,256] f32
    const float* bias = (const float*)d_in[3];  // [128] f32
    float* out = (float*)d_out;                 // [4,10000,128] f32

    const int total4 = BB * NN * CC / 4;
    convert_x_kernel<<<(total4 + 255) / 256, 256>>>(x);
    arrange_W_kernel<<<32, 256>>>(W);

    dim3 grid((NN + TILE - 1) / TILE, BB);
    mrconv_kernel<<<grid, NTHREADS>>>(edge, bias, out);
}